// round 14
// baseline (speedup 1.0000x reference)
#include <cuda_runtime.h>
#include <cuda_fp16.h>
#include <cstdint>

// ---------------- problem shapes ----------------
#define NB    8
#define CIN   256
#define LL    1024
#define VV    25
#define PP    3
#define KWIN  9

// ---------------- gemm-1 tiling -----------------
// CTA: 512 threads / 16 warps; 2 positions, cols = pos*26+v (52 valid of 56).
// M=768 (warp: 3 mtiles), N=56 (7 ntiles), K=256 (16 ksteps).
#define MT    3
#define NT    7
#define KS    16
#define STR_ST 264              // sT row stride (fp16)
// ---------------- gemm-2 (spatial + bias) -------
// M=512 (pos,c), K=80 (p*26 + v; v=25 -> bias col; 78,79 pad), N=32 (w).
#define STR_YH 88
#define KS2   5

// ---------------- smem layout (bytes) -----------
// union: sT (29568) -> Yh (90112) -> zs (51200)
#define SM_ST    0
#define SM_YH    0
#define SM_Z     0
#define SM_GB    90112          // gamma/beta half2 6400 u32
#define SM_B2H   115712         // B2h 32x88 fp16
#define SM_RED   121344
#define SM_TOTAL 121472

// ---------------- device scratch ----------------
__device__ float    g_s[NB*CIN*LL*VV];        // temporal sliding sums
__device__ __half   g_Wf[48*KS*32*8];         // fragment-major W (fp16)
__device__ __half   g_B2h[32*STR_YH];         // Acat + bias-cs columns
__device__ __half   g_Bb[PP*256];             // conv_b fp16
__device__ uint32_t g_GB[256*VV];             // packed (gamma, beta) half2

// ---------------------------------------------------------------------------
// prep: W -> fp16 A-fragments; B2h table (Aeff + cs bias cols); b fp16; GB pack.
// ---------------------------------------------------------------------------
__global__ void prep_kernel(const float* __restrict__ conv_w,
                            const float* __restrict__ A1,
                            const float* __restrict__ A2,
                            const float* __restrict__ A3,
                            const float* __restrict__ ei,
                            const float* __restrict__ conv_b,
                            const float* __restrict__ ln_gamma,
                            const float* __restrict__ ln_beta) {
    const int o = blockIdx.x;       // 0..767
    const int k = threadIdx.x;      // 0..255
    {
        float w = conv_w[o*CIN + k];
        const int mt  = o >> 4, r = o & 15;
        const int ks  = k >> 4, kk = k & 15;
        const int reg = ((r >> 3) & 1) | ((kk >> 3) << 1);
        const int lane = (r & 7) * 4 + ((kk & 7) >> 1);
        const int byt  = kk & 1;
        const size_t off = ((((size_t)mt)*KS + ks)*32 + lane)*8 + reg*2 + byt;
        g_Wf[off] = __float2half(w);
    }
    if (blockIdx.x == 0) {
        // B2h[w][p*26+v] = A_p[v][w]*ei ;  B2h[w][p*26+25] = cs_p[w] ; else 0
        for (int i = k; i < 32*STR_YH; i += 256) {
            const int w2 = i / STR_YH, pv = i % STR_YH;
            float val = 0.f;
            if (w2 < VV && pv < 78) {
                const int p = pv / 26, r = pv % 26;
                const float* Ap = (p==0) ? A1 : ((p==1) ? A2 : A3);
                if (r < VV) {
                    val = Ap[r*VV + w2] * ei[p*VV*VV + r*VV + w2];
                } else {                       // r == 25: column sums
                    float cs = 0.f;
                    for (int v = 0; v < VV; ++v)
                        cs += Ap[v*VV + w2] * ei[p*VV*VV + v*VV + w2];
                    val = cs;
                }
            }
            g_B2h[i] = __float2half(val);
        }
    }
    if (blockIdx.x == 1) {
        for (int i = k; i < PP*256; i += 256) g_Bb[i] = __float2half(conv_b[i]);
    }
    if (blockIdx.x == 2) {
        for (int i = k; i < 256*VV; i += 256) {
            __half2 h = __floats2half2_rn(ln_gamma[i], ln_beta[i]);
            g_GB[i] = *(uint32_t*)&h;
        }
    }
}

// ---------------------------------------------------------------------------
// temporal: causal 9-tap sliding sum over L, 8 segments per (n,ci,v).
// ---------------------------------------------------------------------------
#define NSEG 8
__global__ void temporal_kernel(const float* __restrict__ x) {
    int t = blockIdx.x * blockDim.x + threadIdx.x;
    if (t >= NB*CIN*VV*NSEG) return;
    const int v   = t % VV;
    const int seg = (t / VV) % NSEG;
    const int rc  = t / (VV*NSEG);
    const int base = rc * (LL*VV) + v;
    const int ms = seg * (LL/NSEG);
    const int me = ms + (LL/NSEG);

    float run = 0.f;
    #pragma unroll
    for (int l = (ms >= 8 ? ms - 8 : 0); l < ms; ++l)
        run += x[base + l*VV];
    for (int m = ms; m < me; ++m) {
        run += x[base + m*VV];
        g_s[base + m*VV] = run;
        if (m >= 8) run -= x[base + (m - 8)*VV];
    }
}

// ---------------------------------------------------------------------------
__device__ __forceinline__ void mma16816(float c[4], const uint32_t a[4],
                                         const uint32_t b[2]) {
    asm volatile(
        "mma.sync.aligned.m16n8k16.row.col.f32.f16.f16.f32 "
        "{%0,%1,%2,%3}, {%4,%5,%6,%7}, {%8,%9}, {%0,%1,%2,%3};"
        : "+f"(c[0]), "+f"(c[1]), "+f"(c[2]), "+f"(c[3])
        : "r"(a[0]), "r"(a[1]), "r"(a[2]), "r"(a[3]), "r"(b[0]), "r"(b[1]));
}

// ---------------------------------------------------------------------------
// fused: fp16 GEMM-1 + fp16 GEMM-2 (spatial + bias) + LN + residual.
// ---------------------------------------------------------------------------
__global__ __launch_bounds__(512, 1)
void gemm_kernel(const float* __restrict__ x, float* __restrict__ out) {
    extern __shared__ char smem[];
    __half*   sth = (__half*)(smem + SM_ST);
    __half*   Yh  = (__half*)(smem + SM_YH);
    float*    zs  = (float*)(smem + SM_Z);
    uint32_t* GBs = (uint32_t*)(smem + SM_GB);
    __half*   B2h = (__half*)(smem + SM_B2H);
    float*    red = (float*)(smem + SM_RED);

    const int t = threadIdx.x, wid = t >> 5, lane = t & 31;
    const int n  = blockIdx.x >> 9;
    const int m0 = (blockIdx.x & 511) * 2;

    // ---- const loads ----
    for (int i = t; i < 256*VV; i += 512) GBs[i] = g_GB[i];
    for (int i = t; i < (32*STR_YH)/2; i += 512)
        ((uint32_t*)B2h)[i] = ((const uint32_t*)g_B2h)[i];

    // ---- stage s -> fp16 sT, rows = pos*26+v (coalesced gmem reads) ----
    for (int idx = t; idx < 256*50; idx += 512) {
        const int ci = idx / 50, qq = idx - ci*50;     // qq = pos*25+v
        const int pos = (qq >= VV);
        const float sv = g_s[(size_t)(n*CIN + ci)*(LL*VV) + m0*VV + qq];
        sth[(qq + pos)*STR_ST + ci] = __float2half(sv);
    }
    for (int i = t; i < 6*STR_ST; i += 512) {          // pad rows 25, 51..55
        const int r = i / STR_ST, c2 = i - r*STR_ST;
        const int row = (r == 0) ? 25 : 50 + r;
        sth[row*STR_ST + c2] = __float2half(0.f);
    }
    __syncthreads();

    // -------------------- GEMM-1 (channels, fp16) --------------------
    float acc[MT][NT][4];
    #pragma unroll
    for (int mt = 0; mt < MT; ++mt)
        #pragma unroll
        for (int nt = 0; nt < NT; ++nt)
            #pragma unroll
            for (int r = 0; r < 4; ++r) acc[mt][nt][r] = 0.f;

    {
        const uint4* __restrict__ Wf4 = (const uint4*)g_Wf;
        const int mbase = wid * MT;
        const int brow  = (lane >> 2);
        const int bcol  = 2 * (lane & 3);

        uint4 A[MT];
        #pragma unroll
        for (int mt = 0; mt < MT; ++mt)
            A[mt] = Wf4[((size_t)(mbase + mt)*KS + 0)*32 + lane];

        for (int ks = 0; ks < KS; ++ks) {
            uint4 An[MT];
            if (ks < KS-1) {
                #pragma unroll
                for (int mt = 0; mt < MT; ++mt)
                    An[mt] = Wf4[((size_t)(mbase + mt)*KS + ks + 1)*32 + lane];
            }
            #pragma unroll
            for (int nt = 0; nt < NT; ++nt) {
                const int o = (nt*8 + brow)*STR_ST + ks*16 + bcol;
                uint32_t b2[2];
                b2[0] = *(const uint32_t*)(sth + o);
                b2[1] = *(const uint32_t*)(sth + o + 8);
                #pragma unroll
                for (int mt = 0; mt < MT; ++mt)
                    mma16816(acc[mt][nt], (const uint32_t*)&A[mt], b2);
            }
            if (ks < KS-1) {
                #pragma unroll
                for (int mt = 0; mt < MT; ++mt) A[mt] = An[mt];
            }
        }
    }
    __syncthreads();   // sT dead; region reused as Yh

    // ---- scatter Y -> Yh (half2), K-pad zero, bias columns ----
    {
        *(uint32_t*)&Yh[t*STR_YH + 78] = 0;            // cols 78,79
        const int pos_t = t >> 8, c_t = t & 255;
        const int mm = m0 + pos_t;
        const float nlp = (float)((mm + 1 < KWIN) ? (mm + 1) : KWIN);
        #pragma unroll
        for (int p = 0; p < PP; ++p)                   // bias cols p*26+25
            Yh[t*STR_YH + p*26 + 25] =
                __float2half(nlp * __half2float(g_Bb[p*256 + c_t]));

        #pragma unroll
        for (int mt = 0; mt < MT; ++mt) {
            const int row = wid*48 + mt*16 + (lane >> 2);   // p*256 + c
            const int p  = row >> 8;
            const int c  = row & 255;
            #pragma unroll
            for (int nt = 0; nt < NT; ++nt) {
                const int e = nt*8 + 2*(lane & 3);
                if (e < 52) {
                    const int pos = (e >= 26);
                    const int v   = e - pos*26;
                    const int b0  = ((pos << 8) + c)*STR_YH + p*26 + v;
                    const int b8  = b0 + 8*STR_YH;
                    if (e == 24 || e == 50) {          // pair would hit bias col
                        Yh[b0] = __float2half(acc[mt][nt][0]);
                        Yh[b8] = __float2half(acc[mt][nt][2]);
                    } else {
                        __half2 h0 = __floats2half2_rn(acc[mt][nt][0], acc[mt][nt][1]);
                        __half2 h8 = __floats2half2_rn(acc[mt][nt][2], acc[mt][nt][3]);
                        *(uint32_t*)&Yh[b0] = *(uint32_t*)&h0;
                        *(uint32_t*)&Yh[b8] = *(uint32_t*)&h8;
                    }
                }
            }
        }
    }
    __syncthreads();

    // -------------------- GEMM-2 (spatial + bias, fp16) --------------------
    float acc2[2][4][4];
    #pragma unroll
    for (int mt = 0; mt < 2; ++mt)
        #pragma unroll
        for (int nt = 0; nt < 4; ++nt)
            #pragma unroll
            for (int r = 0; r < 4; ++r) acc2[mt][nt][r] = 0.f;

    {
        const int brow = (lane >> 2);
        const int bcol = 2 * (lane & 3);
        for (int ks2 = 0; ks2 < KS2; ++ks2) {
            uint32_t bf[4][2];
            #pragma unroll
            for (int nt = 0; nt < 4; ++nt) {
                const int o = (nt*8 + brow)*STR_YH + ks2*16 + bcol;
                bf[nt][0] = *(const uint32_t*)(B2h + o);
                bf[nt][1] = *(const uint32_t*)(B2h + o + 8);
            }
            #pragma unroll
            for (int mt = 0; mt < 2; ++mt) {
                const int row0 = (wid*2 + mt)*16 + brow;
                const int base = row0*STR_YH + ks2*16 + bcol;
                uint32_t a[4];
                a[0] = *(const uint32_t*)(Yh + base);
                a[1] = *(const uint32_t*)(Yh + base + 8*STR_YH);
                a[2] = *(const uint32_t*)(Yh + base + 8);
                a[3] = *(const uint32_t*)(Yh + base + 8*STR_YH + 8);
                #pragma unroll
                for (int nt = 0; nt < 4; ++nt)
                    mma16816(acc2[mt][nt], a, bf[nt]);
            }
        }
    }

    // ---- LN stats (bias already inside acc2) ----
    const int pos = wid >> 3;
    float sm_ = 0.f, sq_ = 0.f;
    #pragma unroll
    for (int mt = 0; mt < 2; ++mt)
        #pragma unroll
        for (int r2 = 0; r2 < 2; ++r2)
            #pragma unroll
            for (int nt = 0; nt < 4; ++nt)
                #pragma unroll
                for (int j = 0; j < 2; ++j) {
                    const int w = nt*8 + 2*(lane & 3) + j;
                    if (w < VV) {
                        const float zv = acc2[mt][nt][r2*2 + j];
                        sm_ += zv;
                        sq_  = fmaf(zv, zv, sq_);
                    }
                }
    #pragma unroll
    for (int off = 16; off > 0; off >>= 1) {
        sm_ += __shfl_xor_sync(0xFFFFFFFFu, sm_, off);
        sq_ += __shfl_xor_sync(0xFFFFFFFFu, sq_, off);
    }
    if (lane == 0) { red[wid] = sm_; red[16 + wid] = sq_; }
    __syncthreads();
    float ts = 0.f, tq = 0.f;
    #pragma unroll
    for (int i = 0; i < 8; ++i) { ts += red[pos*8 + i]; tq += red[16 + pos*8 + i]; }
    const float mean = ts * (1.f / 6400.f);
    const float var  = tq * (1.f / 6400.f) - mean*mean;
    const float rstd = rsqrtf(var + 1e-5f);

    // ---- LN apply + relu -> zs[c*50 + pos*25 + w] ----
    #pragma unroll
    for (int mt = 0; mt < 2; ++mt)
        #pragma unroll
        for (int r2 = 0; r2 < 2; ++r2) {
            const int c = ((wid*2 + mt)*16 + (lane >> 2) + 8*r2) & 255;
            #pragma unroll
            for (int nt = 0; nt < 4; ++nt)
                #pragma unroll
                for (int j = 0; j < 2; ++j) {
                    const int w = nt*8 + 2*(lane & 3) + j;
                    if (w < VV) {
                        const float zv = acc2[mt][nt][r2*2 + j];
                        const uint32_t gb = GBs[c*VV + w];
                        const float2 gbf = __half22float2(*(const __half2*)&gb);
                        float h = fmaf((zv - mean)*rstd, gbf.x, gbf.y);
                        zs[c*50 + pos*VV + w] = fmaxf(h, 0.f);
                    }
                }
        }
    __syncthreads();

    // ---- coalesced residual + store ----
    for (int idx = t; idx < 256*50; idx += 512) {
        const int c2 = idx / 50, q = idx - c2*50;
        const size_t a = (size_t)(n*CIN + c2)*(LL*VV) + m0*VV + q;
        out[a] = fmaxf(zs[idx] + x[a], 0.f);
    }
}

// ---------------------------------------------------------------------------
extern "C" void kernel_launch(void* const* d_in, const int* in_sizes, int n_in,
                              void* d_out, int out_size) {
    const float* x      = (const float*)d_in[0];
    const float* A1     = (const float*)d_in[1];
    const float* A2     = (const float*)d_in[2];
    const float* A3     = (const float*)d_in[3];
    const float* conv_w = (const float*)d_in[4];
    const float* conv_b = (const float*)d_in[5];
    const float* gamma  = (const float*)d_in[6];
    const float* beta   = (const float*)d_in[7];
    const float* ei     = (const float*)d_in[8];
    float* out          = (float*)d_out;

    cudaFuncSetAttribute(gemm_kernel,
                         cudaFuncAttributeMaxDynamicSharedMemorySize, SM_TOTAL);

    prep_kernel<<<768, 256>>>(conv_w, A1, A2, A3, ei, conv_b, gamma, beta);
    temporal_kernel<<<(NB*CIN*VV*NSEG + 255) / 256, 256>>>(x);
    gemm_kernel<<<NB * (LL/2), 512, SM_TOTAL>>>(x, out);
}

// round 15
// speedup vs baseline: 1.2871x; 1.2871x over previous
#include <cuda_runtime.h>
#include <cuda_fp16.h>
#include <cstdint>

// ---------------- problem shapes ----------------
#define NB    8
#define CIN   256
#define LL    1024
#define VV    25
#define PP    3
#define KWIN  9
#define APAD  28

// ---------------- gemm-1 tiling -------------------
// CTA: 512 threads / 16 warps; 2 positions packed (cols = pos*25+v, 50 valid).
// M=768 (warp: 48 rows = 3 mtiles), N=56 (7 ntiles), K=256 (16 ksteps).
#define MT    3
#define NT    7
#define KS    16
#define STR_ST 264              // sT row stride (fp16)
// ---------------- gemm-2 (spatial) ---------------
// M=512 (pos,c), K=80 (p*25+v, pad 75..79 = 0), N=32 (w, 25 valid).
#define STR_YH 88               // Yh row stride (fp16)
#define KS2   5

// ---------------- smem layout (bytes) -----------
// union region: sT (29568) -> Yh (90112) -> zs (51200)
#define SM_ST    0
#define SM_YH    0
#define SM_Z     0
#define SM_G     90112          // gamma 6400 f32
#define SM_B2T   115712         // beta  6400 f32
#define SM_BA    141312         // bA    6400 f32
#define SM_B2H   166912         // Acat fp16 32x88
#define SM_RED   172544
#define SM_TOTAL 172672

// ---------------- device scratch ----------------
__device__ float  g_s[NB*CIN*LL*VV];          // temporal sliding sums
__device__ __half g_Wf[48*KS*32*8];           // fragment-major W (fp16)
__device__ float  g_bA[256*VV];               // folded bias
__device__ __half g_B2h[32*STR_YH];           // Acat[(w)][(p*25+v)] fp16, padded zeros

// ---------------------------------------------------------------------------
// prep: W -> fp16 A-fragment layout; Acat fp16 table; folded bias bA.
// ---------------------------------------------------------------------------
__global__ void prep_kernel(const float* __restrict__ conv_w,
                            const float* __restrict__ A1,
                            const float* __restrict__ A2,
                            const float* __restrict__ A3,
                            const float* __restrict__ ei,
                            const float* __restrict__ conv_b) {
    const int o = blockIdx.x;       // 0..767
    const int k = threadIdx.x;      // 0..255
    {
        float w = conv_w[o*CIN + k];
        const int mt  = o >> 4, r = o & 15;
        const int ks  = k >> 4, kk = k & 15;
        const int reg = ((r >> 3) & 1) | ((kk >> 3) << 1);   // a0..a3
        const int lane = (r & 7) * 4 + ((kk & 7) >> 1);
        const int byt  = kk & 1;
        const size_t off = ((((size_t)mt)*KS + ks)*32 + lane)*8 + reg*2 + byt;
        g_Wf[off] = __float2half(w);
    }
    if (blockIdx.x == 0) {
        // Acat[w][p*25+v] = A_p[v][w] * ei[p][v][w]; zero outside valid range
        for (int i = k; i < 32*STR_YH; i += 256) {
            const int w2 = i / STR_YH, pv = i % STR_YH;
            float val = 0.f;
            if (w2 < VV && pv < PP*VV) {
                const int p = pv / VV, v = pv % VV;
                const float* Ap = (p==0) ? A1 : ((p==1) ? A2 : A3);
                val = Ap[v*VV + w2] * ei[p*VV*VV + v*VV + w2];
            }
            g_B2h[i] = __float2half(val);
        }
    }
    if (blockIdx.x == 1) {
        const int c = k;
        for (int w2 = 0; w2 < VV; ++w2) {
            float acc = 0.f;
            for (int p = 0; p < PP; ++p) {
                const float* Ap = (p==0) ? A1 : ((p==1) ? A2 : A3);
                float cs = 0.f;
                for (int v = 0; v < VV; ++v)
                    cs += Ap[v*VV + w2] * ei[p*VV*VV + v*VV + w2];
                acc += conv_b[p*256 + c] * cs;
            }
            g_bA[c*VV + w2] = acc;
        }
    }
}

// ---------------------------------------------------------------------------
// temporal: causal 9-tap sliding sum over L, 8 segments per (n,ci,v).
// ---------------------------------------------------------------------------
#define NSEG 8
__global__ void temporal_kernel(const float* __restrict__ x) {
    int t = blockIdx.x * blockDim.x + threadIdx.x;
    if (t >= NB*CIN*VV*NSEG) return;
    const int v   = t % VV;
    const int seg = (t / VV) % NSEG;
    const int rc  = t / (VV*NSEG);
    const int base = rc * (LL*VV) + v;
    const int ms = seg * (LL/NSEG);
    const int me = ms + (LL/NSEG);

    float run = 0.f;
    #pragma unroll
    for (int l = (ms >= 8 ? ms - 8 : 0); l < ms; ++l)
        run += x[base + l*VV];
    for (int m = ms; m < me; ++m) {
        run += x[base + m*VV];
        g_s[base + m*VV] = run;
        if (m >= 8) run -= x[base + (m - 8)*VV];
    }
}

// ---------------------------------------------------------------------------
__device__ __forceinline__ void mma16816(float c[4], const uint32_t a[4],
                                         const uint32_t b[2]) {
    asm volatile(
        "mma.sync.aligned.m16n8k16.row.col.f32.f16.f16.f32 "
        "{%0,%1,%2,%3}, {%4,%5,%6,%7}, {%8,%9}, {%0,%1,%2,%3};"
        : "+f"(c[0]), "+f"(c[1]), "+f"(c[2]), "+f"(c[3])
        : "r"(a[0]), "r"(a[1]), "r"(a[2]), "r"(a[3]), "r"(b[0]), "r"(b[1]));
}

// ---------------------------------------------------------------------------
// fused: fp16 GEMM-1 (channels) + fp16 GEMM-2 (spatial) + LN + residual.
// One CTA = 2 positions; 512 threads.
// ---------------------------------------------------------------------------
__global__ __launch_bounds__(512, 1)
void gemm_kernel(const float* __restrict__ x,
                 const float* __restrict__ ln_gamma,
                 const float* __restrict__ ln_beta,
                 float* __restrict__ out) {
    extern __shared__ char smem[];
    __half* sth = (__half*)(smem + SM_ST);
    __half* Yh  = (__half*)(smem + SM_YH);
    float*  zs  = (float*)(smem + SM_Z);
    float*  Gs  = (float*)(smem + SM_G);
    float*  Bs  = (float*)(smem + SM_B2T);
    float*  BAs = (float*)(smem + SM_BA);
    __half* B2h = (__half*)(smem + SM_B2H);
    float*  red = (float*)(smem + SM_RED);

    const int t = threadIdx.x, wid = t >> 5, lane = t & 31;
    const int n  = blockIdx.x >> 9;
    const int m0 = (blockIdx.x & 511) * 2;

    // ---- stage s -> fp16 sT (coalesced; both positions contiguous) ----
    for (int idx = t; idx < 256*50; idx += 512) {
        const int ci = idx / 50, q = idx - ci*50;      // q = pos*25+v
        const float sv = g_s[(size_t)(n*CIN + ci)*(LL*VV) + m0*VV + q];
        sth[q*STR_ST + ci] = __float2half(sv);
    }
    for (int i = t; i < 6*STR_ST; i += 512)            // pad rows 50..55
        sth[50*STR_ST + i] = __float2half(0.f);
    __syncthreads();

    // -------------------- GEMM-1 (channels, fp16) --------------------
    float acc[MT][NT][4];
    #pragma unroll
    for (int mt = 0; mt < MT; ++mt)
        #pragma unroll
        for (int nt = 0; nt < NT; ++nt)
            #pragma unroll
            for (int r = 0; r < 4; ++r) acc[mt][nt][r] = 0.f;

    {
        const uint4* __restrict__ Wf4 = (const uint4*)g_Wf;
        const int mbase = wid * MT;
        const int brow  = (lane >> 2);
        const int bcol  = 2 * (lane & 3);

        uint4 A[MT];
        #pragma unroll
        for (int mt = 0; mt < MT; ++mt)
            A[mt] = Wf4[((size_t)(mbase + mt)*KS + 0)*32 + lane];

        for (int ks = 0; ks < KS; ++ks) {
            uint4 An[MT];
            if (ks < KS-1) {
                #pragma unroll
                for (int mt = 0; mt < MT; ++mt)
                    An[mt] = Wf4[((size_t)(mbase + mt)*KS + ks + 1)*32 + lane];
            }
            #pragma unroll
            for (int nt = 0; nt < NT; ++nt) {
                const int o = (nt*8 + brow)*STR_ST + ks*16 + bcol;
                uint32_t b2[2];
                b2[0] = *(const uint32_t*)(sth + o);
                b2[1] = *(const uint32_t*)(sth + o + 8);
                #pragma unroll
                for (int mt = 0; mt < MT; ++mt)
                    mma16816(acc[mt][nt], (const uint32_t*)&A[mt], b2);
            }
            if (ks < KS-1) {
                #pragma unroll
                for (int mt = 0; mt < MT; ++mt) A[mt] = An[mt];
            }
        }
    }

    // ---- const-table loads (deferred: overlap with GEMM-1 tail/scatter) ----
    for (int i = t; i < 256*VV; i += 512) {
        Gs[i]  = ln_gamma[i];
        Bs[i]  = ln_beta[i];
        BAs[i] = g_bA[i];
    }
    for (int i = t; i < (32*STR_YH)/2; i += 512)
        ((uint32_t*)B2h)[i] = ((const uint32_t*)g_B2h)[i];
    __syncthreads();   // sT dead; region reused as Yh

    // ---- scatter Y -> Yh[(pos*256+c)][p*25+v] (fp16); zero K-pad cols ----
    {
        #pragma unroll
        for (int j = 75; j < 80; ++j)                  // one row per thread
            Yh[t*STR_YH + j] = __float2half(0.f);

        #pragma unroll
        for (int mt = 0; mt < MT; ++mt) {
            const int row = wid*48 + mt*16 + (lane >> 2);   // p*256 + c (rows <8)
            const int p  = row >> 8;
            const int c  = row & 255;
            #pragma unroll
            for (int nt = 0; nt < NT; ++nt) {
                #pragma unroll
                for (int j = 0; j < 2; ++j) {
                    const int col = nt*8 + 2*(lane & 3) + j;
                    if (col < 50) {
                        const int pos = (col >= VV);
                        const int v   = col - pos*VV;
                        const int dst = (pos*256 + c)*STR_YH + p*VV + v;
                        Yh[dst]              = __float2half(acc[mt][nt][j]);
                        Yh[dst + 8*STR_YH]   = __float2half(acc[mt][nt][2+j]); // row+8
                    }
                }
            }
        }
    }
    __syncthreads();

    // -------------------- GEMM-2 (spatial, fp16) --------------------
    // M=512: warp wid owns mtiles wid*2, wid*2+1 (rows wid*32..wid*32+31)
    float acc2[2][4][4];
    #pragma unroll
    for (int mt = 0; mt < 2; ++mt)
        #pragma unroll
        for (int nt = 0; nt < 4; ++nt)
            #pragma unroll
            for (int r = 0; r < 4; ++r) acc2[mt][nt][r] = 0.f;

    {
        const int brow = (lane >> 2);
        const int bcol = 2 * (lane & 3);
        for (int ks2 = 0; ks2 < KS2; ++ks2) {
            uint32_t bf[4][2];
            #pragma unroll
            for (int nt = 0; nt < 4; ++nt) {
                const int o = (nt*8 + brow)*STR_YH + ks2*16 + bcol;
                bf[nt][0] = *(const uint32_t*)(B2h + o);
                bf[nt][1] = *(const uint32_t*)(B2h + o + 8);
            }
            #pragma unroll
            for (int mt = 0; mt < 2; ++mt) {
                const int row0 = (wid*2 + mt)*16 + brow;
                const int base = row0*STR_YH + ks2*16 + bcol;
                uint32_t a[4];
                a[0] = *(const uint32_t*)(Yh + base);
                a[1] = *(const uint32_t*)(Yh + base + 8*STR_YH);
                a[2] = *(const uint32_t*)(Yh + base + 8);
                a[3] = *(const uint32_t*)(Yh + base + 8*STR_YH + 8);
                #pragma unroll
                for (int nt = 0; nt < 4; ++nt)
                    mma16816(acc2[mt][nt], a, bf[nt]);
            }
        }
    }

    // ---- bias + LN stats on fragments (warp's rows all in one position) ----
    const int pos = wid >> 3;
    const int m   = m0 + pos;
    const float nl = (float)((m + 1 < KWIN) ? (m + 1) : KWIN);

    float sm_ = 0.f, sq_ = 0.f;
    #pragma unroll
    for (int mt = 0; mt < 2; ++mt) {
        #pragma unroll
        for (int r2 = 0; r2 < 2; ++r2) {               // row vs row+8
            const int c = ((wid*2 + mt)*16 + (lane >> 2) + 8*r2) & 255;
            #pragma unroll
            for (int nt = 0; nt < 4; ++nt) {
                #pragma unroll
                for (int j = 0; j < 2; ++j) {
                    const int w = nt*8 + 2*(lane & 3) + j;
                    if (w < VV) {
                        float zv = acc2[mt][nt][r2*2 + j] + nl*BAs[c*VV + w];
                        acc2[mt][nt][r2*2 + j] = zv;
                        sm_ += zv;
                        sq_  = fmaf(zv, zv, sq_);
                    }
                }
            }
        }
    }
    #pragma unroll
    for (int off = 16; off > 0; off >>= 1) {
        sm_ += __shfl_xor_sync(0xFFFFFFFFu, sm_, off);
        sq_ += __shfl_xor_sync(0xFFFFFFFFu, sq_, off);
    }
    if (lane == 0) { red[wid] = sm_; red[16 + wid] = sq_; }
    __syncthreads();
    float ts = 0.f, tq = 0.f;
    #pragma unroll
    for (int i = 0; i < 8; ++i) { ts += red[pos*8 + i]; tq += red[16 + pos*8 + i]; }
    const float mean = ts * (1.f / 6400.f);
    const float var  = tq * (1.f / 6400.f) - mean*mean;
    const float rstd = rsqrtf(var + 1e-5f);

    // ---- LN + relu -> zs[c*50 + pos*25 + w] ----
    #pragma unroll
    for (int mt = 0; mt < 2; ++mt) {
        #pragma unroll
        for (int r2 = 0; r2 < 2; ++r2) {
            const int c = ((wid*2 + mt)*16 + (lane >> 2) + 8*r2) & 255;
            #pragma unroll
            for (int nt = 0; nt < 4; ++nt) {
                #pragma unroll
                for (int j = 0; j < 2; ++j) {
                    const int w = nt*8 + 2*(lane & 3) + j;
                    if (w < VV) {
                        const float zv = acc2[mt][nt][r2*2 + j];
                        float h = fmaf((zv - mean)*rstd, Gs[c*VV + w], Bs[c*VV + w]);
                        zs[c*50 + pos*VV + w] = fmaxf(h, 0.f);
                    }
                }
            }
        }
    }
    __syncthreads();

    // ---- coalesced residual + store ----
    for (int idx = t; idx < 256*50; idx += 512) {
        const int c2 = idx / 50, q = idx - c2*50;
        const size_t a = (size_t)(n*CIN + c2)*(LL*VV) + m0*VV + q;
        out[a] = fmaxf(zs[idx] + x[a], 0.f);
    }
}

// ---------------------------------------------------------------------------
extern "C" void kernel_launch(void* const* d_in, const int* in_sizes, int n_in,
                              void* d_out, int out_size) {
    const float* x      = (const float*)d_in[0];
    const float* A1     = (const float*)d_in[1];
    const float* A2     = (const float*)d_in[2];
    const float* A3     = (const float*)d_in[3];
    const float* conv_w = (const float*)d_in[4];
    const float* conv_b = (const float*)d_in[5];
    const float* gamma  = (const float*)d_in[6];
    const float* beta   = (const float*)d_in[7];
    const float* ei     = (const float*)d_in[8];
    float* out          = (float*)d_out;

    cudaFuncSetAttribute(gemm_kernel,
                         cudaFuncAttributeMaxDynamicSharedMemorySize, SM_TOTAL);

    prep_kernel<<<768, 256>>>(conv_w, A1, A2, A3, ei, conv_b);
    temporal_kernel<<<(NB*CIN*VV*NSEG + 255) / 256, 256>>>(x);
    gemm_kernel<<<NB * (LL/2), 512, SM_TOTAL>>>(x, gamma, beta, out);
}

// round 17
// speedup vs baseline: 1.3809x; 1.0729x over previous
#include <cuda_runtime.h>
#include <cuda_fp16.h>
#include <cstdint>

// ---------------- problem shapes ----------------
#define NB    8
#define CIN   256
#define LL    1024
#define VV    25
#define PP    3
#define KWIN  9

// ---------------- gemm-1 tiling -------------------
// CTA: 512 threads / 16 warps; 2 positions packed (cols = pos*25+v, 50 valid).
// M=768 (warp: 48 rows = 3 mtiles), N=56 (7 ntiles), K=256 (16 ksteps).
#define MT    3
#define NT    7
#define KS    16
#define STR_ST 264              // sT row stride (fp16)
// ---------------- gemm-2 (spatial) ---------------
// M=512 (pos,c), K=80 (p*25+v, pad 75..79 = 0), N=32 (w, 25 valid).
#define STR_YH 88               // Yh row stride (fp16)
#define KS2   5

// ---------------- smem layout (bytes) -----------
// union region: sT (29568) -> Yh (90112) -> zs (51200)
#define SM_ST    0
#define SM_YH    0
#define SM_Z     0
#define SM_G     90112          // gamma 6400 f32
#define SM_B2T   115712         // beta  6400 f32
#define SM_BA    141312         // bA    6400 f32
#define SM_B2H   166912         // Acat fp16 32x88
#define SM_RED   172544
#define SM_TOTAL 172672

// ---------------- device scratch ----------------
__device__ float  g_s[NB*CIN*LL*VV];          // temporal sliding sums
__device__ __half g_Wf[48*KS*32*8];           // fragment-major W (fp16)
__device__ float  g_bA[256*VV];               // folded bias
__device__ __half g_B2h[32*STR_YH];           // Acat[(w)][(p*25+v)] fp16, padded zeros

// ---------------------------------------------------------------------------
// prep+temporal fused kernel.
// blocks 0..1599     : temporal sliding-sum segments (NSEG=8, 409600 threads)
// blocks 1600..2367  : W -> fp16 m16n8k16 A-fragment pack (o = b-1600)
// blocks 2368..2392  : bA[c][w2] folded bias, w2 = b-2368, c = tid
// block  2393        : B2h (Acat fp16 table)
// ---------------------------------------------------------------------------
#define NSEG 8
#define TBLK_TEMP 1600          // NB*CIN*VV*NSEG / 256 = 409600/256
__global__ void pt_kernel(const float* __restrict__ x,
                          const float* __restrict__ conv_w,
                          const float* __restrict__ A1,
                          const float* __restrict__ A2,
                          const float* __restrict__ A3,
                          const float* __restrict__ ei,
                          const float* __restrict__ conv_b) {
    const int b = blockIdx.x, tid = threadIdx.x;

    if (b < TBLK_TEMP) {
        // temporal: causal 9-tap sliding sum over L
        const int t = b*256 + tid;                 // t < 409600 exactly
        const int v   = t % VV;
        const int seg = (t / VV) % NSEG;
        const int rc  = t / (VV*NSEG);
        const int base = rc * (LL*VV) + v;
        const int ms = seg * (LL/NSEG);
        const int me = ms + (LL/NSEG);
        float run = 0.f;
        #pragma unroll
        for (int l = (ms >= 8 ? ms - 8 : 0); l < ms; ++l)
            run += x[base + l*VV];
        for (int m = ms; m < me; ++m) {
            run += x[base + m*VV];
            g_s[base + m*VV] = run;
            if (m >= 8) run -= x[base + (m - 8)*VV];
        }
    } else if (b < 2368) {
        // W fragment pack
        const int o = b - 1600;                    // 0..767
        const int k = tid;                         // 0..255
        float w = conv_w[o*CIN + k];
        const int mt  = o >> 4, r = o & 15;
        const int ks  = k >> 4, kk = k & 15;
        const int reg = ((r >> 3) & 1) | ((kk >> 3) << 1);
        const int lane = (r & 7) * 4 + ((kk & 7) >> 1);
        const int byt  = kk & 1;
        const size_t off = ((((size_t)mt)*KS + ks)*32 + lane)*8 + reg*2 + byt;
        g_Wf[off] = __float2half(w);
    } else if (b < 2393) {
        // bA: parallel over (w2 = block, c = thread); 75 FMA each
        const int w2 = b - 2368;                   // 0..24
        const int c  = tid;                        // 0..255
        float acc = 0.f;
        #pragma unroll
        for (int p = 0; p < PP; ++p) {
            const float* Ap = (p==0) ? A1 : ((p==1) ? A2 : A3);
            float cs = 0.f;
            #pragma unroll
            for (int v = 0; v < VV; ++v)
                cs += Ap[v*VV + w2] * ei[p*VV*VV + v*VV + w2];
            acc += conv_b[p*256 + c] * cs;
        }
        g_bA[c*VV + w2] = acc;
    } else {
        // B2h: Acat[w][p*25+v] = A_p[v][w]*ei; zero outside valid range
        for (int i = tid; i < 32*STR_YH; i += 256) {
            const int w2 = i / STR_YH, pv = i % STR_YH;
            float val = 0.f;
            if (w2 < VV && pv < PP*VV) {
                const int p = pv / VV, v = pv % VV;
                const float* Ap = (p==0) ? A1 : ((p==1) ? A2 : A3);
                val = Ap[v*VV + w2] * ei[p*VV*VV + v*VV + w2];
            }
            g_B2h[i] = __float2half(val);
        }
    }
}

// ---------------------------------------------------------------------------
__device__ __forceinline__ void mma16816(float c[4], const uint32_t a[4],
                                         const uint32_t b[2]) {
    asm volatile(
        "mma.sync.aligned.m16n8k16.row.col.f32.f16.f16.f32 "
        "{%0,%1,%2,%3}, {%4,%5,%6,%7}, {%8,%9}, {%0,%1,%2,%3};"
        : "+f"(c[0]), "+f"(c[1]), "+f"(c[2]), "+f"(c[3])
        : "r"(a[0]), "r"(a[1]), "r"(a[2]), "r"(a[3]), "r"(b[0]), "r"(b[1]));
}

// ---------------------------------------------------------------------------
// fused: fp16 GEMM-1 (channels) + fp16 GEMM-2 (spatial) + LN + residual.
// One CTA = 2 positions; 512 threads.  (R13 structure — measured best.)
// ---------------------------------------------------------------------------
__global__ __launch_bounds__(512, 1)
void gemm_kernel(const float* __restrict__ x,
                 const float* __restrict__ ln_gamma,
                 const float* __restrict__ ln_beta,
                 float* __restrict__ out) {
    extern __shared__ char smem[];
    __half* sth = (__half*)(smem + SM_ST);
    __half* Yh  = (__half*)(smem + SM_YH);
    float*  zs  = (float*)(smem + SM_Z);
    float*  Gs  = (float*)(smem + SM_G);
    float*  Bs  = (float*)(smem + SM_B2T);
    float*  BAs = (float*)(smem + SM_BA);
    __half* B2h = (__half*)(smem + SM_B2H);
    float*  red = (float*)(smem + SM_RED);

    const int t = threadIdx.x, wid = t >> 5, lane = t & 31;
    const int n  = blockIdx.x >> 9;
    const int m0 = (blockIdx.x & 511) * 2;

    // ---- const loads (early: R13 ordering) ----
    for (int i = t; i < 256*VV; i += 512) {
        Gs[i]  = ln_gamma[i];
        Bs[i]  = ln_beta[i];
        BAs[i] = g_bA[i];
    }
    for (int i = t; i < (32*STR_YH)/2; i += 512)
        ((uint32_t*)B2h)[i] = ((const uint32_t*)g_B2h)[i];

    // ---- stage s -> fp16 sT (coalesced; both positions contiguous) ----
    for (int idx = t; idx < 256*50; idx += 512) {
        const int ci = idx / 50, q = idx - ci*50;      // q = pos*25+v
        const float sv = g_s[(size_t)(n*CIN + ci)*(LL*VV) + m0*VV + q];
        sth[q*STR_ST + ci] = __float2half(sv);
    }
    for (int i = t; i < 6*STR_ST; i += 512)            // pad rows 50..55
        sth[50*STR_ST + i] = __float2half(0.f);
    __syncthreads();

    // -------------------- GEMM-1 (channels, fp16) --------------------
    float acc[MT][NT][4];
    #pragma unroll
    for (int mt = 0; mt < MT; ++mt)
        #pragma unroll
        for (int nt = 0; nt < NT; ++nt)
            #pragma unroll
            for (int r = 0; r < 4; ++r) acc[mt][nt][r] = 0.f;

    {
        const uint4* __restrict__ Wf4 = (const uint4*)g_Wf;
        const int mbase = wid * MT;
        const int brow  = (lane >> 2);
        const int bcol  = 2 * (lane & 3);

        uint4 A[MT];
        #pragma unroll
        for (int mt = 0; mt < MT; ++mt)
            A[mt] = Wf4[((size_t)(mbase + mt)*KS + 0)*32 + lane];

        for (int ks = 0; ks < KS; ++ks) {
            uint4 An[MT];
            if (ks < KS-1) {
                #pragma unroll
                for (int mt = 0; mt < MT; ++mt)
                    An[mt] = Wf4[((size_t)(mbase + mt)*KS + ks + 1)*32 + lane];
            }
            #pragma unroll
            for (int nt = 0; nt < NT; ++nt) {
                const int o = (nt*8 + brow)*STR_ST + ks*16 + bcol;
                uint32_t b2[2];
                b2[0] = *(const uint32_t*)(sth + o);
                b2[1] = *(const uint32_t*)(sth + o + 8);
                #pragma unroll
                for (int mt = 0; mt < MT; ++mt)
                    mma16816(acc[mt][nt], (const uint32_t*)&A[mt], b2);
            }
            if (ks < KS-1) {
                #pragma unroll
                for (int mt = 0; mt < MT; ++mt) A[mt] = An[mt];
            }
        }
    }
    __syncthreads();   // sT dead; region reused as Yh

    // ---- scatter Y -> Yh[(pos*256+c)][p*25+v] (fp16); zero K-pad cols ----
    {
        #pragma unroll
        for (int j = 75; j < 80; ++j)                  // one row per thread
            Yh[t*STR_YH + j] = __float2half(0.f);

        #pragma unroll
        for (int mt = 0; mt < MT; ++mt) {
            const int row = wid*48 + mt*16 + (lane >> 2);   // p*256 + c
            const int p  = row >> 8;
            const int c  = row & 255;
            #pragma unroll
            for (int nt = 0; nt < NT; ++nt) {
                #pragma unroll
                for (int j = 0; j < 2; ++j) {
                    const int col = nt*8 + 2*(lane & 3) + j;
                    if (col < 50) {
                        const int pos = (col >= VV);
                        const int v   = col - pos*VV;
                        const int dst = (pos*256 + c)*STR_YH + p*VV + v;
                        Yh[dst]              = __float2half(acc[mt][nt][j]);
                        Yh[dst + 8*STR_YH]   = __float2half(acc[mt][nt][2+j]);
                    }
                }
            }
        }
    }
    __syncthreads();

    // -------------------- GEMM-2 (spatial, fp16) --------------------
    float acc2[2][4][4];
    #pragma unroll
    for (int mt = 0; mt < 2; ++mt)
        #pragma unroll
        for (int nt = 0; nt < 4; ++nt)
            #pragma unroll
            for (int r = 0; r < 4; ++r) acc2[mt][nt][r] = 0.f;

    {
        const int brow = (lane >> 2);
        const int bcol = 2 * (lane & 3);
        for (int ks2 = 0; ks2 < KS2; ++ks2) {
            uint32_t bf[4][2];
            #pragma unroll
            for (int nt = 0; nt < 4; ++nt) {
                const int o = (nt*8 + brow)*STR_YH + ks2*16 + bcol;
                bf[nt][0] = *(const uint32_t*)(B2h + o);
                bf[nt][1] = *(const uint32_t*)(B2h + o + 8);
            }
            #pragma unroll
            for (int mt = 0; mt < 2; ++mt) {
                const int row0 = (wid*2 + mt)*16 + brow;
                const int base = row0*STR_YH + ks2*16 + bcol;
                uint32_t a[4];
                a[0] = *(const uint32_t*)(Yh + base);
                a[1] = *(const uint32_t*)(Yh + base + 8*STR_YH);
                a[2] = *(const uint32_t*)(Yh + base + 8);
                a[3] = *(const uint32_t*)(Yh + base + 8*STR_YH + 8);
                #pragma unroll
                for (int nt = 0; nt < 4; ++nt)
                    mma16816(acc2[mt][nt], a, bf[nt]);
            }
        }
    }

    // ---- bias + LN stats on fragments ----
    const int pos = wid >> 3;
    const int m   = m0 + pos;
    const float nl = (float)((m + 1 < KWIN) ? (m + 1) : KWIN);

    float sm_ = 0.f, sq_ = 0.f;
    #pragma unroll
    for (int mt = 0; mt < 2; ++mt) {
        #pragma unroll
        for (int r2 = 0; r2 < 2; ++r2) {
            const int c = ((wid*2 + mt)*16 + (lane >> 2) + 8*r2) & 255;
            #pragma unroll
            for (int nt = 0; nt < 4; ++nt) {
                #pragma unroll
                for (int j = 0; j < 2; ++j) {
                    const int w = nt*8 + 2*(lane & 3) + j;
                    if (w < VV) {
                        float zv = acc2[mt][nt][r2*2 + j] + nl*BAs[c*VV + w];
                        acc2[mt][nt][r2*2 + j] = zv;
                        sm_ += zv;
                        sq_  = fmaf(zv, zv, sq_);
                    }
                }
            }
        }
    }
    #pragma unroll
    for (int off = 16; off > 0; off >>= 1) {
        sm_ += __shfl_xor_sync(0xFFFFFFFFu, sm_, off);
        sq_ += __shfl_xor_sync(0xFFFFFFFFu, sq_, off);
    }
    if (lane == 0) { red[wid] = sm_; red[16 + wid] = sq_; }
    __syncthreads();
    float ts = 0.f, tq = 0.f;
    #pragma unroll
    for (int i = 0; i < 8; ++i) { ts += red[pos*8 + i]; tq += red[16 + pos*8 + i]; }
    const float mean = ts * (1.f / 6400.f);
    const float var  = tq * (1.f / 6400.f) - mean*mean;
    const float rstd = rsqrtf(var + 1e-5f);

    // ---- LN + relu -> zs[c*50 + pos*25 + w] ----
    #pragma unroll
    for (int mt = 0; mt < 2; ++mt) {
        #pragma unroll
        for (int r2 = 0; r2 < 2; ++r2) {
            const int c = ((wid*2 + mt)*16 + (lane >> 2) + 8*r2) & 255;
            #pragma unroll
            for (int nt = 0; nt < 4; ++nt) {
                #pragma unroll
                for (int j = 0; j < 2; ++j) {
                    const int w = nt*8 + 2*(lane & 3) + j;
                    if (w < VV) {
                        const float zv = acc2[mt][nt][r2*2 + j];
                        float h = fmaf((zv - mean)*rstd, Gs[c*VV + w], Bs[c*VV + w]);
                        zs[c*50 + pos*VV + w] = fmaxf(h, 0.f);
                    }
                }
            }
        }
    }
    __syncthreads();

    // ---- coalesced residual + store ----
    for (int idx = t; idx < 256*50; idx += 512) {
        const int c2 = idx / 50, q = idx - c2*50;
        const size_t a = (size_t)(n*CIN + c2)*(LL*VV) + m0*VV + q;
        out[a] = fmaxf(zs[idx] + x[a], 0.f);
    }
}

// ---------------------------------------------------------------------------
extern "C" void kernel_launch(void* const* d_in, const int* in_sizes, int n_in,
                              void* d_out, int out_size) {
    const float* x      = (const float*)d_in[0];
    const float* A1     = (const float*)d_in[1];
    const float* A2     = (const float*)d_in[2];
    const float* A3     = (const float*)d_in[3];
    const float* conv_w = (const float*)d_in[4];
    const float* conv_b = (const float*)d_in[5];
    const float* gamma  = (const float*)d_in[6];
    const float* beta   = (const float*)d_in[7];
    const float* ei     = (const float*)d_in[8];
    float* out          = (float*)d_out;

    cudaFuncSetAttribute(gemm_kernel,
                         cudaFuncAttributeMaxDynamicSharedMemorySize, SM_TOTAL);

    pt_kernel<<<2394, 256>>>(x, conv_w, A1, A2, A3, ei, conv_b);
    gemm_kernel<<<NB * (LL/2), 512, SM_TOTAL>>>(x, gamma, beta, out);
}